// round 15
// baseline (speedup 1.0000x reference)
#include <cuda_runtime.h>
#include <cuda_fp16.h>
#include <math.h>
#include <stdint.h>

#define NB 2048   // batch
#define NF 512    // features
#define NH 256    // hidden
#define NE 64     // experts
#define NK 8      // top-k

typedef unsigned int u32;
typedef unsigned long long u64;

// ---------------- scratch (no allocation allowed) ----------------
__device__ int   g_counts[NE];
__device__ int   g_tok[NE * NB];
__device__ float g_wt[NE * NB];
__device__ float g_escale[NE];
__device__ float g_efinv[NE];
__device__ float g_xinv[NB];
__device__ float g_gw[NE * NF];        // gate matrix: emb @ pw  [e][f]
__device__ float g_gc[NE];             // gate bias:   pb . emb_e
__device__ float g_L[NB * NE];         // raw gate logits (pre-bias)
__device__ float g_S[NB * NE];         // raw sims (pre-normalization)
// fp16 buffers: X rounded, W rounded + transposed
__device__ __half g_xh[NB * NF];                   // 2MB
__device__ __half g_wth[(size_t)NE * NF * NF];     // 33.5MB, layout [e][n][k]

// ---------------- PTX helpers ----------------
__device__ __forceinline__ uint32_t smem_to_u32(const void* p) {
    uint32_t a;
    asm("{ .reg .u64 t; cvta.to.shared.u64 t, %1; cvt.u32.u64 %0, t; }"
        : "=r"(a) : "l"(p));
    return a;
}
__device__ __forceinline__ void cp16(uint32_t dst, const void* src, int srcsize) {
    asm volatile("cp.async.cg.shared.global [%0], [%1], 16, %2;"
                 :: "r"(dst), "l"(src), "r"(srcsize));
}
#define CP_COMMIT() asm volatile("cp.async.commit_group;" ::: "memory")
#define CP_WAIT(n)  asm volatile("cp.async.wait_group %0;" :: "n"(n) : "memory")

__device__ __forceinline__ void ldm_x4(u32& r0, u32& r1, u32& r2, u32& r3, u32 addr) {
    asm volatile("ldmatrix.sync.aligned.m8n8.x4.shared.b16 {%0,%1,%2,%3}, [%4];"
                 : "=r"(r0), "=r"(r1), "=r"(r2), "=r"(r3) : "r"(addr));
}
__device__ __forceinline__ void mma_f16(float& c0, float& c1, float& c2, float& c3,
                                        u32 a0, u32 a1, u32 a2, u32 a3,
                                        u32 b0, u32 b1) {
    asm volatile("mma.sync.aligned.m16n8k16.row.col.f32.f16.f16.f32 "
                 "{%0,%1,%2,%3}, {%4,%5,%6,%7}, {%8,%9}, {%0,%1,%2,%3};"
                 : "+f"(c0), "+f"(c1), "+f"(c2), "+f"(c3)
                 : "r"(a0), "r"(a1), "r"(a2), "r"(a3), "r"(b0), "r"(b1));
}
__device__ __forceinline__ void fma2(u64& acc, u64 a, u64 b) {
    asm("fma.rn.f32x2 %0, %1, %2, %0;" : "+l"(acc) : "l"(a), "l"(b));
}
__device__ __forceinline__ u64 pack_dup(float x) {
    u64 p;
    asm("mov.b64 %0, {%1, %1};" : "=l"(p) : "f"(x));
    return p;
}
__device__ __forceinline__ float2 unpack2(u64 v) {
    float2 r;
    asm("mov.b64 {%0, %1}, %2;" : "=f"(r.x), "=f"(r.y) : "l"(v));
    return r;
}

// ---------------- fp16 helpers ----------------
__device__ __forceinline__ u32 pack_h2(float a, float b) {
    __half ha = __float2half(a), hb = __float2half(b);
    return (u32)__half_as_ushort(ha) | ((u32)__half_as_ushort(hb) << 16);
}

// ---------------- kernel A: fused zero(out) + X->fp16 ----------------------
__global__ void __launch_bounds__(256)
zero_convert_x(const float* __restrict__ feat, float4* __restrict__ out) {
    const int tid = blockIdx.x * 256 + threadIdx.x;     // 131072 threads
    const float4 z = make_float4(0.f, 0.f, 0.f, 0.f);
    out[tid]          = z;
    out[tid + 131072] = z;
    u32* xh = (u32*)g_xh;
    #pragma unroll
    for (int i = 0; i < 4; i++) {
        int p = tid + 131072 * i;                        // 524288 pairs
        float2 v = *(const float2*)(feat + 2 * p);
        xh[p] = pack_h2(v.x, v.y);
    }
}

// ---------------- kernel B: fused per-expert init + gate precompute --------
// block e: g_gw[e][:], g_gc[e], g_counts[e]=0, g_escale[e], g_efinv[e]
__global__ void __launch_bounds__(256)
init_pregate(const float* __restrict__ pw, const float* __restrict__ pb,
             const float* __restrict__ emb, const float* __restrict__ ef,
             const float* __restrict__ trust, const float* __restrict__ dt) {
    __shared__ float es[NH];
    __shared__ float red[256];
    const int e   = blockIdx.x;
    const int tid = threadIdx.x;
    es[tid] = emb[(size_t)e * NH + tid];
    {
        float a = ef[(size_t)e * NF + tid];
        float b = ef[(size_t)e * NF + tid + 256];
        red[tid] = a * a + b * b;
    }
    __syncthreads();
    // tree-reduce ef norm
    #pragma unroll
    for (int s = 128; s > 0; s >>= 1) {
        if (tid < s) red[tid] += red[tid + s];
        __syncthreads();
    }
    if (tid == 0) {
        g_counts[e] = 0;
        g_escale[e] = trust[e] * fmaxf(0.1f, expf(-0.005f * dt[e]));
        g_efinv[e]  = 1.0f / fmaxf(sqrtf(red[0]), 1e-8f);
    }

    // gate matrix rows
    const int f0 = tid, f1 = tid + 256;
    float a0 = 0.f, a1 = 0.f;
    #pragma unroll 8
    for (int h = 0; h < NH; h++) {
        float ev = es[h];
        a0 += ev * pw[(size_t)h * NF + f0];
        a1 += ev * pw[(size_t)h * NF + f1];
    }
    g_gw[e * NF + f0] = a0;
    g_gw[e * NF + f1] = a1;

    if (tid < 32) {
        float s = 0.f;
        #pragma unroll
        for (int h = tid; h < NH; h += 32) s += pb[h] * es[h];
        #pragma unroll
        for (int off = 16; off > 0; off >>= 1)
            s += __shfl_xor_sync(0xffffffffu, s, off);
        if (tid == 0) g_gc[e] = s;
    }
}

// ---------------- kernel 1c: round + transpose W -> [e][n][k] fp16 ---------
__global__ void __launch_bounds__(256)
convert_w(const float* __restrict__ fw) {
    __shared__ float s[64][65];
    const int e  = blockIdx.z;
    const int k0 = blockIdx.x * 64;
    const int n0 = blockIdx.y * 64;
    const int tid = threadIdx.x;
    const float* src = fw + ((size_t)e * NF + k0) * NF + n0;
    #pragma unroll
    for (int i = 0; i < 16; i++) {
        int idx = tid + 256 * i;
        int kl = idx >> 6, nl = idx & 63;
        s[kl][nl] = src[(size_t)kl * NF + nl];
    }
    __syncthreads();
    u32* wh = (u32*)g_wth;
    #pragma unroll
    for (int i = 0; i < 8; i++) {
        int idx = tid + 256 * i;
        int nl = idx >> 5;
        int kp = (idx & 31) * 2;
        size_t off = (((size_t)e * NF + n0 + nl) * NF + k0 + kp) >> 1;
        wh[off] = pack_h2(s[kp][nl], s[kp + 1][nl]);
    }
}

// ---------------- kernel 2a: routing GEMM halves ---------------------------
#define V5_XSS 516
#define V5_BSS 68
#define V5_XS  0
#define V5_BS  (16 * V5_XSS)                  // 8256
#define ROUT_SMEM ((V5_BS + 32 * V5_BSS) * 4) // ~41.7KB

__global__ void __launch_bounds__(256)
route_gemm(const float* __restrict__ feat, const float* __restrict__ ef) {
    extern __shared__ float sm[];
    float* xs = sm + V5_XS;
    float* bs = sm + V5_BS;

    const int tid  = threadIdx.x;
    const int half = blockIdx.x;
    const int t0   = blockIdx.y * 16;

    const float4* feat4 = (const float4*)feat;
    #pragma unroll
    for (int i = 0; i < 8; i++) {
        int idx = tid + 256 * i;
        int t   = idx >> 7;
        int q   = idx & 127;
        float4 v = feat4[(size_t)(t0 + t) * 128 + q];
        *(float4*)(xs + t * V5_XSS + q * 4) = v;
    }
    __syncthreads();

    if (half == 1 && tid < 16) {
        const float* xr = xs + tid * V5_XSS;
        float s = 0.f;
        #pragma unroll 8
        for (int i = 0; i < NF / 4; i++) {
            float4 v = *(const float4*)(xr + i * 4);
            s += v.x * v.x + v.y * v.y + v.z * v.z + v.w * v.w;
        }
        g_xinv[t0 + tid] = 1.0f / fmaxf(sqrtf(s), 1e-8f);
    }

    const float* bsrc = half ? ef : g_gw;
    const int t  = tid & 15;
    const int cg = tid >> 4;
    u64 acc0 = 0ULL, acc1 = 0ULL;

    for (int k0 = 0; k0 < NF; k0 += 32) {
        #pragma unroll
        for (int i = 0; i < 2; i++) {
            int idx = tid + 256 * i;
            int row = idx >> 3;
            int kq  = idx & 7;
            float4 v = *(const float4*)(bsrc + (size_t)row * NF + k0 + kq * 4);
            bs[(kq * 4 + 0) * V5_BSS + row] = v.x;
            bs[(kq * 4 + 1) * V5_BSS + row] = v.y;
            bs[(kq * 4 + 2) * V5_BSS + row] = v.z;
            bs[(kq * 4 + 3) * V5_BSS + row] = v.w;
        }
        __syncthreads();
        #pragma unroll
        for (int kk = 0; kk < 32; kk++) {
            u64 xp = pack_dup(xs[t * V5_XSS + k0 + kk]);
            ulonglong2 w = *(const ulonglong2*)(bs + kk * V5_BSS + cg * 4);
            fma2(acc0, xp, w.x);
            fma2(acc1, xp, w.y);
        }
        __syncthreads();
    }

    float* dst = (half ? g_S : g_L) + (size_t)(t0 + t) * NE + cg * 4;
    float2 a0 = unpack2(acc0), a1 = unpack2(acc1);
    dst[0] = a0.x; dst[1] = a0.y; dst[2] = a1.x; dst[3] = a1.y;
}

// ---------------- kernel 2b: score + top-8 + softmax + scatter -------------
__global__ void __launch_bounds__(256)
route_topk() {
    const int tid  = threadIdx.x;
    const int lane = tid & 31;
    const int tok  = blockIdx.x * 8 + (tid >> 5);
    const float xi = g_xinv[tok];

    float s0, s1;
    {
        int e0 = lane, e1 = lane + 32;
        float gate0 = 1.0f / (1.0f + expf(-(g_L[(size_t)tok * NE + e0] + g_gc[e0]) * 0.0625f));
        float gate1 = 1.0f / (1.0f + expf(-(g_L[(size_t)tok * NE + e1] + g_gc[e1]) * 0.0625f));
        float sim0  = fmaxf(g_S[(size_t)tok * NE + e0] * xi * g_efinv[e0], 0.f);
        float sim1  = fmaxf(g_S[(size_t)tok * NE + e1] * xi * g_efinv[e1], 0.f);
        s0 = gate0 * sim0 * g_escale[e0];
        s1 = gate1 * sim1 * g_escale[e1];
    }
    const int e0 = lane, e1 = lane + 32;

    float vk[NK];
    int   ik[NK];
    #pragma unroll
    for (int k = 0; k < NK; k++) {
        float v; int ix;
        if (s0 >= s1) { v = s0; ix = e0; }
        else          { v = s1; ix = e1; }
        #pragma unroll
        for (int off = 16; off > 0; off >>= 1) {
            float ov = __shfl_down_sync(0xffffffffu, v, off);
            int   oi = __shfl_down_sync(0xffffffffu, ix, off);
            if (ov > v || (ov == v && oi < ix)) { v = ov; ix = oi; }
        }
        v  = __shfl_sync(0xffffffffu, v, 0);
        ix = __shfl_sync(0xffffffffu, ix, 0);
        vk[k] = v; ik[k] = ix;
        if (ix == e0) s0 = -1e30f;
        if (ix == e1) s1 = -1e30f;
    }
    float m = vk[0], sum = 0.f, w[NK];
    #pragma unroll
    for (int k = 0; k < NK; k++) { w[k] = expf(vk[k] - m); sum += w[k]; }
    float inv = 1.0f / sum;
    if (lane < NK) {
        int e = ik[lane];
        int slot = atomicAdd(&g_counts[e], 1);
        g_tok[e * NB + slot] = tok;
        g_wt[e * NB + slot]  = w[lane] * inv;
    }
}

// ---------------- kernel 3: fp16 single-pass MoE GEMM, 3-stage pipeline ----
// CTA tile 128 tok x 128 cols, K chunks of 64. Stage = A(16K)+B(16K) = 32KB,
// TRIPLE buffered (99KB smem) -> still 2 CTAs/SM. Two chunks of compute now
// cover each cp.async load's latency.
#define MG_DATA    1024
#define MG_STAGE   32768
#define MG_A       0
#define MG_B       16384
#define MG_SMEM    (MG_DATA + 3 * MG_STAGE)   // 99328 bytes

__global__ void __launch_bounds__(256, 2)
moe_gemm_mma(const float* __restrict__ fb, float* __restrict__ out) {
    const int e    = blockIdx.y;
    const int n0   = blockIdx.x * 128;
    const int tile = blockIdx.z;
    const int cnt  = g_counts[e];
    if (tile * 128 >= cnt) return;

    extern __shared__ char smem[];
    const uint32_t sb = smem_to_u32(smem);
    const int tid = threadIdx.x;

    int*   toks = (int*)(smem);
    float* wts  = (float*)(smem + 512);
    {
        int s = tile * 128 + tid;
        if (tid < 128) {
            if (s < cnt) { toks[tid] = g_tok[e * NB + s]; wts[tid] = g_wt[e * NB + s]; }
            else         { toks[tid] = -1;                wts[tid] = 0.f; }
        }
    }
    __syncthreads();

    const int srow  = tid >> 1;
    const int spart = (tid & 1) * 4;
    const int stok  = toks[srow];
    const int asz   = (stok >= 0) ? 16 : 0;
    const uint4* aS = (const uint4*)(g_xh + (size_t)max(stok, 0) * NF);
    const uint4* bS = (const uint4*)(g_wth + ((size_t)e * NF + n0 + srow) * NF);
    const uint32_t srowb = sb + MG_DATA + srow * 128;
    const int      ssw   = (srow & 7) * 16;

    #define PREFETCH(c)                                                          \
    do {                                                                         \
        const uint32_t _d = srowb + ((c) % 3) * MG_STAGE;                        \
        _Pragma("unroll")                                                        \
        for (int j = 0; j < 4; j++) {                                            \
            const int c16 = spart + j;                                           \
            const uint32_t off = (uint32_t)((c16 * 16) ^ ssw);                   \
            cp16(_d + MG_A + off, aS + (c) * 8 + c16, asz);                      \
            cp16(_d + MG_B + off, bS + (c) * 8 + c16, 16);                       \
        }                                                                        \
        CP_COMMIT();                                                             \
    } while (0)

    PREFETCH(0);
    PREFETCH(1);

    const int lid = tid & 31;
    const int wid = tid >> 5;
    const int wm  = wid & 1;
    const int wn  = wid >> 1;

    float acc[4][4][4];
    #pragma unroll
    for (int mt = 0; mt < 4; mt++)
        #pragma unroll
        for (int nt = 0; nt < 4; nt++)
            #pragma unroll
            for (int q = 0; q < 4; q++) acc[mt][nt][q] = 0.f;

    const int fa_row = (lid & 15);
    const int fa_hi  = (lid >> 4);

    #pragma unroll 1
    for (int c = 0; c < 8; c++) {
        if (c + 2 < 8) { PREFETCH(c + 2); CP_WAIT(2); }
        else if (c == 6) { CP_WAIT(1); }
        else if (c == 7) { CP_WAIT(0); }
        __syncthreads();

        const uint32_t base = sb + MG_DATA + (c % 3) * MG_STAGE;

        #pragma unroll
        for (int ks = 0; ks < 4; ks++) {
            const int c16 = ks * 2 + fa_hi;
            u32 ah[4][4];
            #pragma unroll
            for (int mt = 0; mt < 4; mt++) {
                const int r = wm * 64 + mt * 16 + fa_row;
                const uint32_t off = r * 128 + (uint32_t)((c16 * 16) ^ ((r & 7) * 16));
                ldm_x4(ah[mt][0], ah[mt][1], ah[mt][2], ah[mt][3], base + MG_A + off);
            }
            u32 bh[2][4];
            #pragma unroll
            for (int p = 0; p < 2; p++) {
                const int r = wn * 32 + p * 16 + fa_row;
                const uint32_t off = r * 128 + (uint32_t)((c16 * 16) ^ ((r & 7) * 16));
                ldm_x4(bh[p][0], bh[p][1], bh[p][2], bh[p][3], base + MG_B + off);
            }
            #pragma unroll
            for (int mt = 0; mt < 4; mt++) {
                #pragma unroll
                for (int nt = 0; nt < 4; nt++) {
                    const int p = nt >> 1, h = nt & 1;
                    float* cc = acc[mt][nt];
                    mma_f16(cc[0], cc[1], cc[2], cc[3],
                            ah[mt][0], ah[mt][1], ah[mt][2], ah[mt][3],
                            bh[p][h], bh[p][h + 2]);
                }
            }
        }
        __syncthreads();
    }

    const float* fbr = fb + (size_t)e * NF + n0;
    #pragma unroll
    for (int mt = 0; mt < 4; mt++) {
        const int r0 = wm * 64 + mt * 16 + (lid >> 2);
        const int r1 = r0 + 8;
        const int tok0 = toks[r0], tok1 = toks[r1];
        const float w0 = wts[r0],  w1 = wts[r1];
        #pragma unroll
        for (int nt = 0; nt < 4; nt++) {
            const int cb = wn * 32 + nt * 8 + (lid & 3) * 2;
            const float b0v = fbr[cb], b1v = fbr[cb + 1];
            const float* cc = acc[mt][nt];
            if (tok0 >= 0) {
                float* orow = out + (size_t)tok0 * NF + n0 + cb;
                atomicAdd(orow + 0, w0 * (cc[0] + b0v));
                atomicAdd(orow + 1, w0 * (cc[1] + b1v));
            }
            if (tok1 >= 0) {
                float* orow = out + (size_t)tok1 * NF + n0 + cb;
                atomicAdd(orow + 0, w1 * (cc[2] + b0v));
                atomicAdd(orow + 1, w1 * (cc[3] + b1v));
            }
        }
    }
}

// ---------------- launch (forked-stream graph; moe is 6th launch) ----------
extern "C" void kernel_launch(void* const* d_in, const int* in_sizes, int n_in,
                              void* d_out, int out_size) {
    const float* feat  = (const float*)d_in[0];  // [B,F]
    const float* pw    = (const float*)d_in[1];  // [H,F]
    const float* pb    = (const float*)d_in[2];  // [H]
    const float* emb   = (const float*)d_in[3];  // [E,H]
    const float* ef    = (const float*)d_in[4];  // [E,F]
    const float* trust = (const float*)d_in[5];  // [E]
    const float* dt    = (const float*)d_in[6];  // [E]
    const float* fw    = (const float*)d_in[7];  // [E,F,F]
    const float* fb    = (const float*)d_in[8];  // [E,F]
    float* out = (float*)d_out;

    static bool init_done = false;
    static cudaStream_t s1, s2;
    static cudaEvent_t evRoot, evJ1, evJ2;
    if (!init_done) {
        cudaFuncSetAttribute(route_gemm,
                             cudaFuncAttributeMaxDynamicSharedMemorySize, ROUT_SMEM);
        cudaFuncSetAttribute(moe_gemm_mma,
                             cudaFuncAttributeMaxDynamicSharedMemorySize, MG_SMEM);
        cudaStreamCreateWithFlags(&s1, cudaStreamNonBlocking);
        cudaStreamCreateWithFlags(&s2, cudaStreamNonBlocking);
        cudaEventCreateWithFlags(&evRoot, cudaEventDisableTiming);
        cudaEventCreateWithFlags(&evJ1,   cudaEventDisableTiming);
        cudaEventCreateWithFlags(&evJ2,   cudaEventDisableTiming);
        init_done = true;
    }

    // fork
    cudaEventRecord(evRoot, 0);
    cudaStreamWaitEvent(s1, evRoot, 0);
    cudaStreamWaitEvent(s2, evRoot, 0);

    // side 1: weight round+transpose (DRAM-bound)
    convert_w<<<dim3(8, 8, NE), 256, 0, s1>>>(fw);                      // #1
    // side 2: fused zero + X conversion
    zero_convert_x<<<512, 256, 0, s2>>>(feat, (float4*)out);            // #2
    // main: fused init+pregate -> routing GEMM -> topk
    init_pregate<<<NE, 256>>>(pw, pb, emb, ef, trust, dt);              // #3
    route_gemm<<<dim3(2, NB / 16), 256, ROUT_SMEM>>>(feat, ef);         // #4
    route_topk<<<NB / 8, 256>>>();                                      // #5

    // moe needs s1 (W) + s2 (X, out zeroed) + main (routing)
    cudaEventRecord(evJ1, s1);
    cudaEventRecord(evJ2, s2);
    cudaStreamWaitEvent(0, evJ1, 0);
    cudaStreamWaitEvent(0, evJ2, 0);
    moe_gemm_mma<<<dim3(4, NE, NB / 128), 256, MG_SMEM>>>(fb, out);     // #6
}

// round 17
// speedup vs baseline: 1.0009x; 1.0009x over previous
#include <cuda_runtime.h>
#include <cuda_fp16.h>
#include <math.h>
#include <stdint.h>

#define NB 2048   // batch
#define NF 512    // features
#define NH 256    // hidden
#define NE 64     // experts
#define NK 8      // top-k

typedef unsigned int u32;
typedef unsigned long long u64;

// ---------------- scratch (no allocation allowed) ----------------
__device__ int   g_counts[NE];
__device__ int   g_tok[NE * NB];
__device__ float g_wt[NE * NB];
__device__ float g_escale[NE];
__device__ float g_efinv[NE];
__device__ float g_xinv[NB];
__device__ float g_gw[NE * NF];        // gate matrix: emb @ pw  [e][f]
__device__ float g_gc[NE];             // gate bias:   pb . emb_e
__device__ float g_L[NB * NE];         // raw gate logits (pre-bias)
__device__ float g_S[NB * NE];         // raw sims (pre-normalization)
// fp16 buffers: X rounded, W rounded + transposed
__device__ __half g_xh[NB * NF];                   // 2MB
__device__ __half g_wth[(size_t)NE * NF * NF];     // 33.5MB, layout [e][n][k]

// ---------------- PTX helpers ----------------
__device__ __forceinline__ uint32_t smem_to_u32(const void* p) {
    uint32_t a;
    asm("{ .reg .u64 t; cvta.to.shared.u64 t, %1; cvt.u32.u64 %0, t; }"
        : "=r"(a) : "l"(p));
    return a;
}
__device__ __forceinline__ void cp16(uint32_t dst, const void* src, int srcsize) {
    asm volatile("cp.async.cg.shared.global [%0], [%1], 16, %2;"
                 :: "r"(dst), "l"(src), "r"(srcsize));
}
#define CP_COMMIT() asm volatile("cp.async.commit_group;" ::: "memory")
#define CP_WAIT(n)  asm volatile("cp.async.wait_group %0;" :: "n"(n) : "memory")

__device__ __forceinline__ void ldm_x4(u32& r0, u32& r1, u32& r2, u32& r3, u32 addr) {
    asm volatile("ldmatrix.sync.aligned.m8n8.x4.shared.b16 {%0,%1,%2,%3}, [%4];"
                 : "=r"(r0), "=r"(r1), "=r"(r2), "=r"(r3) : "r"(addr));
}
__device__ __forceinline__ void mma_f16(float& c0, float& c1, float& c2, float& c3,
                                        u32 a0, u32 a1, u32 a2, u32 a3,
                                        u32 b0, u32 b1) {
    asm volatile("mma.sync.aligned.m16n8k16.row.col.f32.f16.f16.f32 "
                 "{%0,%1,%2,%3}, {%4,%5,%6,%7}, {%8,%9}, {%0,%1,%2,%3};"
                 : "+f"(c0), "+f"(c1), "+f"(c2), "+f"(c3)
                 : "r"(a0), "r"(a1), "r"(a2), "r"(a3), "r"(b0), "r"(b1));
}
__device__ __forceinline__ void fma2(u64& acc, u64 a, u64 b) {
    asm("fma.rn.f32x2 %0, %1, %2, %0;" : "+l"(acc) : "l"(a), "l"(b));
}
__device__ __forceinline__ u64 pack_dup(float x) {
    u64 p;
    asm("mov.b64 %0, {%1, %1};" : "=l"(p) : "f"(x));
    return p;
}
__device__ __forceinline__ float2 unpack2(u64 v) {
    float2 r;
    asm("mov.b64 {%0, %1}, %2;" : "=f"(r.x), "=f"(r.y) : "l"(v));
    return r;
}

// ---------------- fp16 helpers ----------------
__device__ __forceinline__ u32 pack_h2(float a, float b) {
    __half ha = __float2half(a), hb = __float2half(b);
    return (u32)__half_as_ushort(ha) | ((u32)__half_as_ushort(hb) << 16);
}

// ---------------- kernel A: fused zero(out) + X->fp16 ----------------------
__global__ void __launch_bounds__(256)
zero_convert_x(const float* __restrict__ feat, float4* __restrict__ out) {
    const int tid = blockIdx.x * 256 + threadIdx.x;     // 131072 threads
    const float4 z = make_float4(0.f, 0.f, 0.f, 0.f);
    out[tid]          = z;
    out[tid + 131072] = z;
    u32* xh = (u32*)g_xh;
    #pragma unroll
    for (int i = 0; i < 4; i++) {
        int p = tid + 131072 * i;                        // 524288 pairs
        float2 v = *(const float2*)(feat + 2 * p);
        xh[p] = pack_h2(v.x, v.y);
    }
}

// ---------------- kernel B: fused per-expert init + gate precompute --------
__global__ void __launch_bounds__(256)
init_pregate(const float* __restrict__ pw, const float* __restrict__ pb,
             const float* __restrict__ emb, const float* __restrict__ ef,
             const float* __restrict__ trust, const float* __restrict__ dt) {
    __shared__ float es[NH];
    __shared__ float red[256];
    const int e   = blockIdx.x;
    const int tid = threadIdx.x;
    es[tid] = emb[(size_t)e * NH + tid];
    {
        float a = ef[(size_t)e * NF + tid];
        float b = ef[(size_t)e * NF + tid + 256];
        red[tid] = a * a + b * b;
    }
    __syncthreads();
    #pragma unroll
    for (int s = 128; s > 0; s >>= 1) {
        if (tid < s) red[tid] += red[tid + s];
        __syncthreads();
    }
    if (tid == 0) {
        g_counts[e] = 0;
        g_escale[e] = trust[e] * fmaxf(0.1f, expf(-0.005f * dt[e]));
        g_efinv[e]  = 1.0f / fmaxf(sqrtf(red[0]), 1e-8f);
    }

    const int f0 = tid, f1 = tid + 256;
    float a0 = 0.f, a1 = 0.f;
    #pragma unroll 8
    for (int h = 0; h < NH; h++) {
        float ev = es[h];
        a0 += ev * pw[(size_t)h * NF + f0];
        a1 += ev * pw[(size_t)h * NF + f1];
    }
    g_gw[e * NF + f0] = a0;
    g_gw[e * NF + f1] = a1;

    if (tid < 32) {
        float s = 0.f;
        #pragma unroll
        for (int h = tid; h < NH; h += 32) s += pb[h] * es[h];
        #pragma unroll
        for (int off = 16; off > 0; off >>= 1)
            s += __shfl_xor_sync(0xffffffffu, s, off);
        if (tid == 0) g_gc[e] = s;
    }
}

// ---------------- kernel 1c: round + transpose W -> [e][n][k] fp16 ---------
__global__ void __launch_bounds__(256)
convert_w(const float* __restrict__ fw) {
    __shared__ float s[64][65];
    const int e  = blockIdx.z;
    const int k0 = blockIdx.x * 64;
    const int n0 = blockIdx.y * 64;
    const int tid = threadIdx.x;
    const float* src = fw + ((size_t)e * NF + k0) * NF + n0;
    #pragma unroll
    for (int i = 0; i < 16; i++) {
        int idx = tid + 256 * i;
        int kl = idx >> 6, nl = idx & 63;
        s[kl][nl] = src[(size_t)kl * NF + nl];
    }
    __syncthreads();
    u32* wh = (u32*)g_wth;
    #pragma unroll
    for (int i = 0; i < 8; i++) {
        int idx = tid + 256 * i;
        int nl = idx >> 5;
        int kp = (idx & 31) * 2;
        size_t off = (((size_t)e * NF + n0 + nl) * NF + k0 + kp) >> 1;
        wh[off] = pack_h2(s[kp][nl], s[kp + 1][nl]);
    }
}

// ---------------- kernel 2a: routing GEMM halves (v6: K-chunk 64, ILP) -----
// grid (2, 128): half 0 -> L = X @ g_gw^T, half 1 -> S = X @ ef^T (+xinv).
// 16 tok x 64 cols per CTA, K chunks of 64, kk unrolled by 4 with register
// staging. __launch_bounds__(256,2) frees the register budget for MLP.
#define V6_XSS 516
#define V6_BSS 68
#define V6_XS  0
#define V6_BS  (16 * V6_XSS)                  // 8256
#define ROUT_SMEM ((V6_BS + 64 * V6_BSS) * 4) // 50432 B

__global__ void __launch_bounds__(256, 2)
route_gemm(const float* __restrict__ feat, const float* __restrict__ ef) {
    extern __shared__ float sm[];
    float* xs = sm + V6_XS;
    float* bs = sm + V6_BS;

    const int tid  = threadIdx.x;
    const int half = blockIdx.x;
    const int t0   = blockIdx.y * 16;

    const float4* feat4 = (const float4*)feat;
    #pragma unroll
    for (int i = 0; i < 8; i++) {
        int idx = tid + 256 * i;
        int t   = idx >> 7;
        int q   = idx & 127;
        float4 v = feat4[(size_t)(t0 + t) * 128 + q];
        *(float4*)(xs + t * V6_XSS + q * 4) = v;
    }
    __syncthreads();

    if (half == 1 && tid < 16) {
        const float* xr = xs + tid * V6_XSS;
        float s = 0.f;
        #pragma unroll 8
        for (int i = 0; i < NF / 4; i++) {
            float4 v = *(const float4*)(xr + i * 4);
            s += v.x * v.x + v.y * v.y + v.z * v.z + v.w * v.w;
        }
        g_xinv[t0 + tid] = 1.0f / fmaxf(sqrtf(s), 1e-8f);
    }

    const float* bsrc = half ? ef : g_gw;
    const int t  = tid & 15;
    const int cg = tid >> 4;
    u64 acc0 = 0ULL, acc1 = 0ULL;

    for (int k0 = 0; k0 < NF; k0 += 64) {
        // stage B chunk: 64 rows x 64 k, transposed -> bs[kk][row]
        #pragma unroll
        for (int i = 0; i < 4; i++) {
            int idx = tid + 256 * i;          // 0..1023
            int row = idx >> 4;               // 0..63
            int kq  = idx & 15;               // float4 index within 64 k
            float4 v = *(const float4*)(bsrc + (size_t)row * NF + k0 + kq * 4);
            bs[(kq * 4 + 0) * V6_BSS + row] = v.x;
            bs[(kq * 4 + 1) * V6_BSS + row] = v.y;
            bs[(kq * 4 + 2) * V6_BSS + row] = v.z;
            bs[(kq * 4 + 3) * V6_BSS + row] = v.w;
        }
        __syncthreads();
        const float* xrow = xs + t * V6_XSS + k0;
        const float* wcol = bs + cg * 4;
        #pragma unroll 4
        for (int kk = 0; kk < 64; kk += 4) {
            // batched register staging: 4 x-values + 4 w-vectors, then 8 fma2
            float x0 = xrow[kk + 0], x1 = xrow[kk + 1];
            float x2 = xrow[kk + 2], x3 = xrow[kk + 3];
            ulonglong2 w0 = *(const ulonglong2*)(wcol + (kk + 0) * V6_BSS);
            ulonglong2 w1 = *(const ulonglong2*)(wcol + (kk + 1) * V6_BSS);
            ulonglong2 w2 = *(const ulonglong2*)(wcol + (kk + 2) * V6_BSS);
            ulonglong2 w3 = *(const ulonglong2*)(wcol + (kk + 3) * V6_BSS);
            u64 xp0 = pack_dup(x0), xp1 = pack_dup(x1);
            u64 xp2 = pack_dup(x2), xp3 = pack_dup(x3);
            fma2(acc0, xp0, w0.x); fma2(acc1, xp0, w0.y);
            fma2(acc0, xp1, w1.x); fma2(acc1, xp1, w1.y);
            fma2(acc0, xp2, w2.x); fma2(acc1, xp2, w2.y);
            fma2(acc0, xp3, w3.x); fma2(acc1, xp3, w3.y);
        }
        __syncthreads();
    }

    float* dst = (half ? g_S : g_L) + (size_t)(t0 + t) * NE + cg * 4;
    float2 a0 = unpack2(acc0), a1 = unpack2(acc1);
    dst[0] = a0.x; dst[1] = a0.y; dst[2] = a1.x; dst[3] = a1.y;
}

// ---------------- kernel 2b: score + top-8 + softmax + scatter -------------
__global__ void __launch_bounds__(256)
route_topk() {
    const int tid  = threadIdx.x;
    const int lane = tid & 31;
    const int tok  = blockIdx.x * 8 + (tid >> 5);
    const float xi = g_xinv[tok];

    float s0, s1;
    {
        int e0 = lane, e1 = lane + 32;
        float gate0 = 1.0f / (1.0f + expf(-(g_L[(size_t)tok * NE + e0] + g_gc[e0]) * 0.0625f));
        float gate1 = 1.0f / (1.0f + expf(-(g_L[(size_t)tok * NE + e1] + g_gc[e1]) * 0.0625f));
        float sim0  = fmaxf(g_S[(size_t)tok * NE + e0] * xi * g_efinv[e0], 0.f);
        float sim1  = fmaxf(g_S[(size_t)tok * NE + e1] * xi * g_efinv[e1], 0.f);
        s0 = gate0 * sim0 * g_escale[e0];
        s1 = gate1 * sim1 * g_escale[e1];
    }
    const int e0 = lane, e1 = lane + 32;

    float vk[NK];
    int   ik[NK];
    #pragma unroll
    for (int k = 0; k < NK; k++) {
        float v; int ix;
        if (s0 >= s1) { v = s0; ix = e0; }
        else          { v = s1; ix = e1; }
        #pragma unroll
        for (int off = 16; off > 0; off >>= 1) {
            float ov = __shfl_down_sync(0xffffffffu, v, off);
            int   oi = __shfl_down_sync(0xffffffffu, ix, off);
            if (ov > v || (ov == v && oi < ix)) { v = ov; ix = oi; }
        }
        v  = __shfl_sync(0xffffffffu, v, 0);
        ix = __shfl_sync(0xffffffffu, ix, 0);
        vk[k] = v; ik[k] = ix;
        if (ix == e0) s0 = -1e30f;
        if (ix == e1) s1 = -1e30f;
    }
    float m = vk[0], sum = 0.f, w[NK];
    #pragma unroll
    for (int k = 0; k < NK; k++) { w[k] = expf(vk[k] - m); sum += w[k]; }
    float inv = 1.0f / sum;
    if (lane < NK) {
        int e = ik[lane];
        int slot = atomicAdd(&g_counts[e], 1);
        g_tok[e * NB + slot] = tok;
        g_wt[e * NB + slot]  = w[lane] * inv;
    }
}

// ---------------- kernel 3: fp16 single-pass MoE GEMM (R14 2-stage) --------
#define MG_DATA    1024
#define MG_STAGE   32768
#define MG_A       0
#define MG_B       16384
#define MG_SMEM    (MG_DATA + 2 * MG_STAGE)   // 66560 bytes

__global__ void __launch_bounds__(256, 2)
moe_gemm_mma(const float* __restrict__ fb, float* __restrict__ out) {
    const int e    = blockIdx.y;
    const int n0   = blockIdx.x * 128;
    const int tile = blockIdx.z;
    const int cnt  = g_counts[e];
    if (tile * 128 >= cnt) return;

    extern __shared__ char smem[];
    const uint32_t sb = smem_to_u32(smem);
    const int tid = threadIdx.x;

    int*   toks = (int*)(smem);
    float* wts  = (float*)(smem + 512);
    {
        int s = tile * 128 + tid;
        if (tid < 128) {
            if (s < cnt) { toks[tid] = g_tok[e * NB + s]; wts[tid] = g_wt[e * NB + s]; }
            else         { toks[tid] = -1;                wts[tid] = 0.f; }
        }
    }
    __syncthreads();

    const int srow  = tid >> 1;
    const int spart = (tid & 1) * 4;
    const int stok  = toks[srow];
    const int asz   = (stok >= 0) ? 16 : 0;
    const uint4* aS = (const uint4*)(g_xh + (size_t)max(stok, 0) * NF);
    const uint4* bS = (const uint4*)(g_wth + ((size_t)e * NF + n0 + srow) * NF);
    const uint32_t srowb = sb + MG_DATA + srow * 128;
    const int      ssw   = (srow & 7) * 16;

    #define PREFETCH(c)                                                          \
    do {                                                                         \
        const uint32_t _d = srowb + ((c) & 1) * MG_STAGE;                        \
        _Pragma("unroll")                                                        \
        for (int j = 0; j < 4; j++) {                                            \
            const int c16 = spart + j;                                           \
            const uint32_t off = (uint32_t)((c16 * 16) ^ ssw);                   \
            cp16(_d + MG_A + off, aS + (c) * 8 + c16, asz);                      \
            cp16(_d + MG_B + off, bS + (c) * 8 + c16, 16);                       \
        }                                                                        \
    } while (0)

    PREFETCH(0);
    CP_COMMIT();

    const int lid = tid & 31;
    const int wid = tid >> 5;
    const int wm  = wid & 1;
    const int wn  = wid >> 1;

    float acc[4][4][4];
    #pragma unroll
    for (int mt = 0; mt < 4; mt++)
        #pragma unroll
        for (int nt = 0; nt < 4; nt++)
            #pragma unroll
            for (int q = 0; q < 4; q++) acc[mt][nt][q] = 0.f;

    const int fa_row = (lid & 15);
    const int fa_hi  = (lid >> 4);

    for (int c = 0; c < 8; c++) {
        if (c < 7) { PREFETCH(c + 1); CP_COMMIT(); CP_WAIT(1); }
        else       { CP_WAIT(0); }
        __syncthreads();

        const uint32_t base = sb + MG_DATA + (c & 1) * MG_STAGE;

        #pragma unroll
        for (int ks = 0; ks < 4; ks++) {
            const int c16 = ks * 2 + fa_hi;
            u32 ah[4][4];
            #pragma unroll
            for (int mt = 0; mt < 4; mt++) {
                const int r = wm * 64 + mt * 16 + fa_row;
                const uint32_t off = r * 128 + (uint32_t)((c16 * 16) ^ ((r & 7) * 16));
                ldm_x4(ah[mt][0], ah[mt][1], ah[mt][2], ah[mt][3], base + MG_A + off);
            }
            u32 bh[2][4];
            #pragma unroll
            for (int p = 0; p < 2; p++) {
                const int r = wn * 32 + p * 16 + fa_row;
                const uint32_t off = r * 128 + (uint32_t)((c16 * 16) ^ ((r & 7) * 16));
                ldm_x4(bh[p][0], bh[p][1], bh[p][2], bh[p][3], base + MG_B + off);
            }
            #pragma unroll
            for (int mt = 0; mt < 4; mt++) {
                #pragma unroll
                for (int nt = 0; nt < 4; nt++) {
                    const int p = nt >> 1, h = nt & 1;
                    float* cc = acc[mt][nt];
                    mma_f16(cc[0], cc[1], cc[2], cc[3],
                            ah[mt][0], ah[mt][1], ah[mt][2], ah[mt][3],
                            bh[p][h], bh[p][h + 2]);
                }
            }
        }
        __syncthreads();
    }

    const float* fbr = fb + (size_t)e * NF + n0;
    #pragma unroll
    for (int mt = 0; mt < 4; mt++) {
        const int r0 = wm * 64 + mt * 16 + (lid >> 2);
        const int r1 = r0 + 8;
        const int tok0 = toks[r0], tok1 = toks[r1];
        const float w0 = wts[r0],  w1 = wts[r1];
        #pragma unroll
        for (int nt = 0; nt < 4; nt++) {
            const int cb = wn * 32 + nt * 8 + (lid & 3) * 2;
            const float b0v = fbr[cb], b1v = fbr[cb + 1];
            const float* cc = acc[mt][nt];
            if (tok0 >= 0) {
                float* orow = out + (size_t)tok0 * NF + n0 + cb;
                atomicAdd(orow + 0, w0 * (cc[0] + b0v));
                atomicAdd(orow + 1, w0 * (cc[1] + b1v));
            }
            if (tok1 >= 0) {
                float* orow = out + (size_t)tok1 * NF + n0 + cb;
                atomicAdd(orow + 0, w1 * (cc[2] + b0v));
                atomicAdd(orow + 1, w1 * (cc[3] + b1v));
            }
        }
    }
}

// ---------------- launch (forked-stream graph; moe is 6th launch) ----------
extern "C" void kernel_launch(void* const* d_in, const int* in_sizes, int n_in,
                              void* d_out, int out_size) {
    const float* feat  = (const float*)d_in[0];  // [B,F]
    const float* pw    = (const float*)d_in[1];  // [H,F]
    const float* pb    = (const float*)d_in[2];  // [H]
    const float* emb   = (const float*)d_in[3];  // [E,H]
    const float* ef    = (const float*)d_in[4];  // [E,F]
    const float* trust = (const float*)d_in[5];  // [E]
    const float* dt    = (const float*)d_in[6];  // [E]
    const float* fw    = (const float*)d_in[7];  // [E,F,F]
    const float* fb    = (const float*)d_in[8];  // [E,F]
    float* out = (float*)d_out;

    static bool init_done = false;
    static cudaStream_t s1, s2;
    static cudaEvent_t evRoot, evJ1, evJ2;
    if (!init_done) {
        cudaFuncSetAttribute(route_gemm,
                             cudaFuncAttributeMaxDynamicSharedMemorySize, ROUT_SMEM);
        cudaFuncSetAttribute(moe_gemm_mma,
                             cudaFuncAttributeMaxDynamicSharedMemorySize, MG_SMEM);
        cudaStreamCreateWithFlags(&s1, cudaStreamNonBlocking);
        cudaStreamCreateWithFlags(&s2, cudaStreamNonBlocking);
        cudaEventCreateWithFlags(&evRoot, cudaEventDisableTiming);
        cudaEventCreateWithFlags(&evJ1,   cudaEventDisableTiming);
        cudaEventCreateWithFlags(&evJ2,   cudaEventDisableTiming);
        init_done = true;
    }

    // fork
    cudaEventRecord(evRoot, 0);
    cudaStreamWaitEvent(s1, evRoot, 0);
    cudaStreamWaitEvent(s2, evRoot, 0);

    // side 1: weight round+transpose (DRAM-bound)
    convert_w<<<dim3(8, 8, NE), 256, 0, s1>>>(fw);                      // #1
    // side 2: fused zero + X conversion
    zero_convert_x<<<512, 256, 0, s2>>>(feat, (float4*)out);            // #2
    // main: fused init+pregate -> routing GEMM -> topk
    init_pregate<<<NE, 256>>>(pw, pb, emb, ef, trust, dt);              // #3
    route_gemm<<<dim3(2, NB / 16), 256, ROUT_SMEM>>>(feat, ef);         // #4
    route_topk<<<NB / 8, 256>>>();                                      // #5

    // moe needs s1 (W) + s2 (X, out zeroed) + main (routing)
    cudaEventRecord(evJ1, s1);
    cudaEventRecord(evJ2, s2);
    cudaStreamWaitEvent(0, evJ1, 0);
    cudaStreamWaitEvent(0, evJ2, 0);
    moe_gemm_mma<<<dim3(4, NE, NB / 128), 256, MG_SMEM>>>(fb, out);     // #6
}